// round 15
// baseline (speedup 1.0000x reference)
#include <cuda_runtime.h>
#include <cuda_fp16.h>

#define NV 100000
#define NE 1600000
#define NTILES 782            // ceil(NV/128)
#define NBLOCKS 592           // 148 SMs x 4 co-resident blocks (safe on 152 too)
#define NTHREADS 256

// Packed per-vertex projection record: one 32B L2 sector per gather.
struct __align__(32) PRec16 {
    uint4 w;            // P0 fp32 | h2(P1,P2) | h2(P3,P4) | h2(P5,P6)
    unsigned int w4;    // h2(P7,P8)
    unsigned int pad[3];
};
struct __align__(32) VRec {
    float4 acc;   // (sum_m0, sum_mv1, sum_mv2, deg) — RED target
    float4 self;  // (selfMag, selfT1, selfT2, -)
};

__device__ PRec16 g_P16[NV];
__device__ VRec   g_vs[NV];
__device__ unsigned int g_arrive = 0;
__device__ unsigned int g_gen = 0;

__device__ __forceinline__ unsigned int pack2(float a, float b) {
    __half2 h = __floats2half2_rn(a, b);
    return *(unsigned int*)&h;
}

// Grid-wide barrier: safe because all NBLOCKS are co-resident
// (__launch_bounds__(256,4) x 148 SMs >= 592).
__device__ __forceinline__ void grid_sync() {
    __syncthreads();
    if (threadIdx.x == 0) {
        __threadfence();                       // publish this block's writes
        unsigned int gen = atomicAdd(&g_gen, 0);
        __threadfence();
        unsigned int ticket = atomicAdd(&g_arrive, 1);
        if (ticket == NBLOCKS - 1) {
            g_arrive = 0;
            __threadfence();
            atomicAdd(&g_gen, 1);
        } else {
            while (atomicAdd(&g_gen, 0) == gen) __nanosleep(64);
        }
    }
    __syncthreads();
}

__device__ __forceinline__ void edge_msg(int src, float t, float g,
                                         float& m0, float& mv1, float& mv2) {
    float st, ct, sg, cg;
    __sincosf(t, &st, &ct);
    __sincosf(g, &sg, &cg);
    float cdt = fmaf(ct, cg, st * sg);     // cos(t-g)
    float sdt = fmaf(st, cg, -ct * sg);    // sin(t-g)
    float c2 = fmaf(ct, cdt, -st * sdt);   // cos(2t-g)
    float s2 = fmaf(st, cdt, ct * sdt);    // sin(2t-g)

    const PRec16& pr = g_P16[src];
    uint4 w = pr.w;
    unsigned int w4 = pr.w4;
    float  p0  = __uint_as_float(w.x);
    float2 p12 = __half22float2(*(const __half2*)&w.y);
    float2 p34 = __half22float2(*(const __half2*)&w.z);
    float2 p56 = __half22float2(*(const __half2*)&w.w);
    float2 p78 = __half22float2(*(const __half2*)&w4);

    m0  = p0 + fmaf(p12.x, cdt, p12.y * sdt);
    mv1 = fmaf(p34.x, ct, -p34.y * st) + fmaf(p56.x, cg, -p56.y * sg)
        + fmaf(p78.x, c2, p78.y * s2);
    mv2 = fmaf(p34.x, st, p34.y * ct) + fmaf(p56.x, sg, p56.y * cg)
        + fmaf(-p78.y, c2, p78.x * s2);
}

// ---------------------------------------------------------------------------
// Single fused kernel: precompute -> barrier -> edges -> barrier -> finalize.
// ---------------------------------------------------------------------------
__global__ void __launch_bounds__(NTHREADS, 4)
fused_kernel(const float* __restrict__ x,
             const int* __restrict__ edge_index,
             const float* __restrict__ angles,
             const float* __restrict__ transporters,
             const float* __restrict__ e1,
             const float* __restrict__ e2,
             const float* __restrict__ w_self0,
             const float* __restrict__ w_n00,
             const float* __restrict__ w_n10,
             const float* __restrict__ w_self11,
             const float* __restrict__ w_n01,
             const float* __restrict__ w_n11,
             float* __restrict__ out) {
    __shared__ float4 sx4[128 * 13];

    // ===================== Phase 1: per-vertex projections ==================
    for (int tile = blockIdx.x; tile < NTILES; tile += NBLOCKS) {
        int base = tile * 128;
        int nV = NV - base; if (nV > 128) nV = 128;

        const float4* xg = (const float4*)(x + (size_t)base * 48);
        int nf4 = nV * 12;
        for (int j = threadIdx.x; j < nf4; j += NTHREADS)
            sx4[(j / 12) * 13 + (j % 12)] = xg[j];
        __syncthreads();

        // 128 vertices handled by threads 0..127; threads 128..255 idle here
        // (they shared the staging load above).
        if (threadIdx.x < 128 && threadIdx.x < nV) {
            int v = base + threadIdx.x;
            const float4* xv4 = &sx4[threadIdx.x * 13];

            float P0 = 0.f, P3 = 0.f, P4 = 0.f, P9 = 0.f;
#pragma unroll
            for (int i4 = 0; i4 < 4; i4++) {
                float4 q = xv4[i4];
                float vals[4] = {q.x, q.y, q.z, q.w};
#pragma unroll
                for (int k = 0; k < 4; k++) {
                    int i = i4 * 4 + k;
                    float xi = vals[k];
                    P0 = fmaf(xi, __ldg(&w_n00[i]), P0);
                    P3 = fmaf(xi, __ldg(&w_n01[2 * i + 0]), P3);
                    P4 = fmaf(xi, __ldg(&w_n01[2 * i + 1]), P4);
                    P9 = fmaf(xi, __ldg(&w_self0[i]), P9);
                }
            }

            float a0 = 0.f, b0 = 0.f, a1 = 0.f, b1 = 0.f;
            float ap = 0.f, bp = 0.f, aq = 0.f, bq = 0.f;
            float ar = 0.f, br = 0.f, as_ = 0.f, bs = 0.f;
            float t1s = 0.f, t2s = 0.f;

#define CHAN(c, a, b)                                                \
    {                                                                \
        float w0 = __ldg(&w_n10[2 * (c) + 0]);                       \
        float w1 = __ldg(&w_n10[2 * (c) + 1]);                       \
        a0 = fmaf(a, w0, a0); b0 = fmaf(b, w0, b0);                  \
        a1 = fmaf(a, w1, a1); b1 = fmaf(b, w1, b1);                  \
        float p = __ldg(&w_n11[4 * (c) + 0]);                        \
        float q = __ldg(&w_n11[4 * (c) + 1]);                        \
        float r = __ldg(&w_n11[4 * (c) + 2]);                        \
        float s = __ldg(&w_n11[4 * (c) + 3]);                        \
        ap = fmaf(a, p, ap); bp = fmaf(b, p, bp);                    \
        aq = fmaf(a, q, aq); bq = fmaf(b, q, bq);                    \
        ar = fmaf(a, r, ar); br = fmaf(b, r, br);                    \
        as_ = fmaf(a, s, as_); bs = fmaf(b, s, bs);                  \
        float sa = __ldg(&w_self11[2 * (c) + 0]);                    \
        float sb = __ldg(&w_self11[2 * (c) + 1]);                    \
        t1s = fmaf(a, sa, t1s); t1s = fmaf(-b, sb, t1s);             \
        t2s = fmaf(b, sa, t2s); t2s = fmaf(a, sb, t2s);              \
    }
#pragma unroll
            for (int c4 = 0; c4 < 8; c4++) {
                float4 q4 = xv4[4 + c4];
                CHAN(2 * c4 + 0, q4.x, q4.y)
                CHAN(2 * c4 + 1, q4.z, q4.w)
            }
#undef CHAN

            PRec16 rec;
            rec.w = make_uint4(__float_as_uint(P0),
                               pack2(a0 + b1, b0 - a1),
                               pack2(P3, P4),
                               pack2(ap - bq, bp + aq));
            rec.w4 = pack2(ar + bs, br - as_);
            rec.pad[0] = rec.pad[1] = rec.pad[2] = 0u;
            g_P16[v] = rec;

            VRec vr;
            vr.acc  = make_float4(0.f, 0.f, 0.f, 0.f);
            vr.self = make_float4(P9, t1s, t2s, 0.f);
            g_vs[v] = vr;
        }
        __syncthreads();   // protect smem reuse on next tile
    }

    grid_sync();

    // ===================== Phase 2: edge messages ===========================
    {
        const int NQ = NE / 4;   // 400000 quads
        for (int i = blockIdx.x * NTHREADS + threadIdx.x; i < NQ;
             i += NBLOCKS * NTHREADS) {
            int4   s4 = ((const int4*)edge_index)[i];
            int4   d4 = ((const int4*)(edge_index + NE))[i];
            float4 t4 = ((const float4*)angles)[i];
            float4 g4 = ((const float4*)transporters)[i];

            float m0, mv1, mv2;
#define DO_EDGE(SRC, DST, T, G)                                              \
    edge_msg(SRC, T, G, m0, mv1, mv2);                                       \
    asm volatile("red.relaxed.gpu.global.add.v4.f32 [%0], {%1, %2, %3, %4};" \
                 :: "l"(&g_vs[DST].acc), "f"(m0), "f"(mv1), "f"(mv2),        \
                    "f"(1.0f) : "memory");
            DO_EDGE(s4.x, d4.x, t4.x, g4.x)
            DO_EDGE(s4.y, d4.y, t4.y, g4.y)
            DO_EDGE(s4.z, d4.z, t4.z, g4.z)
            DO_EDGE(s4.w, d4.w, t4.w, g4.w)
#undef DO_EDGE
        }
    }

    grid_sync();

    // ===================== Phase 3: finalize ================================
    for (int j = blockIdx.x * NTHREADS + threadIdx.x; j < NV * 3;
         j += NBLOCKS * NTHREADS) {
        int v = j / 3;
        VRec vr = g_vs[v];
        float inv = 1.0f / fmaxf(vr.acc.w, 1.0f);

        float mag = fmaf(vr.acc.x, inv, vr.self.x);
        float t1  = fmaf(vr.acc.y, inv, vr.self.y);
        float t2  = fmaf(vr.acc.z, inv, vr.self.z);
        float scale = 2.0f / (1.0f + __expf(-mag));

        out[j] = fmaf(t1, e1[j], t2 * e2[j]) * scale;
    }
}

extern "C" void kernel_launch(void* const* d_in, const int* in_sizes, int n_in,
                              void* d_out, int out_size) {
    const float* x            = (const float*)d_in[0];
    const int*   edge_index   = (const int*)d_in[1];
    const float* angles       = (const float*)d_in[2];
    const float* transporters = (const float*)d_in[3];
    const float* e1           = (const float*)d_in[4];
    const float* e2           = (const float*)d_in[5];
    const float* w_self0      = (const float*)d_in[6];
    const float* w_n00        = (const float*)d_in[7];
    const float* w_n10        = (const float*)d_in[8];
    const float* w_self11     = (const float*)d_in[9];
    const float* w_n01        = (const float*)d_in[10];
    const float* w_n11        = (const float*)d_in[11];
    float*       out          = (float*)d_out;

    fused_kernel<<<NBLOCKS, NTHREADS>>>(
        x, edge_index, angles, transporters, e1, e2,
        w_self0, w_n00, w_n10, w_self11, w_n01, w_n11, out);
}

// round 16
// speedup vs baseline: 1.0356x; 1.0356x over previous
#include <cuda_runtime.h>
#include <cuda_fp16.h>

#define NV 100000
#define NE 1600000
#define VERT_BLOCKS ((NV + 127) / 128)

// Packed per-vertex projection record: one 32B L2 sector per gather.
struct __align__(32) PRec16 {
    uint4 w;            // P0 fp32 | h2(P1,P2) | h2(P3,P4) | h2(P5,P6)
    unsigned int w4;    // h2(P7,P8)
    unsigned int pad[3];
};
struct __align__(32) VRec {
    float4 acc;   // (sum_m0, sum_mv1, sum_mv2, deg) — RED target
    float4 self;  // (selfMag, selfT1, selfT2, -)
};

__device__ PRec16 g_P16[NV];
__device__ VRec   g_vs[NV];

__device__ __forceinline__ unsigned int pack2(float a, float b) {
    __half2 h = __floats2half2_rn(a, b);
    return *(unsigned int*)&h;
}
__device__ __forceinline__ void pdl_trigger() {
    asm volatile("griddepcontrol.launch_dependents;");
}
__device__ __forceinline__ void pdl_wait() {
    asm volatile("griddepcontrol.wait;" ::: "memory");
}

// ---------------------------------------------------------------------------
// Kernel 1 (R14): per-vertex projections, all-128-bit smem path.
// Triggers the dependent edge kernel immediately so its stream loads overlap.
// ---------------------------------------------------------------------------
__global__ void __launch_bounds__(128)
precompute_kernel(const float* __restrict__ x,
                  const float* __restrict__ w_self0,
                  const float* __restrict__ w_n00,
                  const float* __restrict__ w_n10,
                  const float* __restrict__ w_self11,
                  const float* __restrict__ w_n01,
                  const float* __restrict__ w_n11) {
    pdl_trigger();   // let the edge kernel start pulling its streams now

    __shared__ float4 sx4[128 * 13];

    int base = blockIdx.x * 128;
    int nV = NV - base; if (nV > 128) nV = 128;

    const float4* xg = (const float4*)(x + (size_t)base * 48);
    int nf4 = nV * 12;
    for (int j = threadIdx.x; j < nf4; j += 128) {
        sx4[(j / 12) * 13 + (j % 12)] = xg[j];
    }
    __syncthreads();

    int v = base + threadIdx.x;
    if (v >= NV) return;
    const float4* xv4 = &sx4[threadIdx.x * 13];

    float P0 = 0.f, P3 = 0.f, P4 = 0.f, P9 = 0.f;
#pragma unroll
    for (int i4 = 0; i4 < 4; i4++) {
        float4 q = xv4[i4];
        float vals[4] = {q.x, q.y, q.z, q.w};
#pragma unroll
        for (int k = 0; k < 4; k++) {
            int i = i4 * 4 + k;
            float xi = vals[k];
            P0 = fmaf(xi, __ldg(&w_n00[i]), P0);
            P3 = fmaf(xi, __ldg(&w_n01[2 * i + 0]), P3);
            P4 = fmaf(xi, __ldg(&w_n01[2 * i + 1]), P4);
            P9 = fmaf(xi, __ldg(&w_self0[i]), P9);
        }
    }

    float a0 = 0.f, b0 = 0.f, a1 = 0.f, b1 = 0.f;
    float ap = 0.f, bp = 0.f, aq = 0.f, bq = 0.f;
    float ar = 0.f, br = 0.f, as_ = 0.f, bs = 0.f;
    float t1s = 0.f, t2s = 0.f;

#define CHAN(c, a, b)                                                \
    {                                                                \
        float w0 = __ldg(&w_n10[2 * (c) + 0]);                       \
        float w1 = __ldg(&w_n10[2 * (c) + 1]);                       \
        a0 = fmaf(a, w0, a0); b0 = fmaf(b, w0, b0);                  \
        a1 = fmaf(a, w1, a1); b1 = fmaf(b, w1, b1);                  \
        float p = __ldg(&w_n11[4 * (c) + 0]);                        \
        float q = __ldg(&w_n11[4 * (c) + 1]);                        \
        float r = __ldg(&w_n11[4 * (c) + 2]);                        \
        float s = __ldg(&w_n11[4 * (c) + 3]);                        \
        ap = fmaf(a, p, ap); bp = fmaf(b, p, bp);                    \
        aq = fmaf(a, q, aq); bq = fmaf(b, q, bq);                    \
        ar = fmaf(a, r, ar); br = fmaf(b, r, br);                    \
        as_ = fmaf(a, s, as_); bs = fmaf(b, s, bs);                  \
        float sa = __ldg(&w_self11[2 * (c) + 0]);                    \
        float sb = __ldg(&w_self11[2 * (c) + 1]);                    \
        t1s = fmaf(a, sa, t1s); t1s = fmaf(-b, sb, t1s);             \
        t2s = fmaf(b, sa, t2s); t2s = fmaf(a, sb, t2s);              \
    }

#pragma unroll
    for (int c4 = 0; c4 < 8; c4++) {
        float4 q4 = xv4[4 + c4];
        CHAN(2 * c4 + 0, q4.x, q4.y)
        CHAN(2 * c4 + 1, q4.z, q4.w)
    }
#undef CHAN

    PRec16 rec;
    rec.w = make_uint4(__float_as_uint(P0),
                       pack2(a0 + b1, b0 - a1),     // (P1, P2)
                       pack2(P3, P4),               // (P3, P4)
                       pack2(ap - bq, bp + aq));    // (P5, P6)
    rec.w4 = pack2(ar + bs, br - as_);              // (P7, P8)
    rec.pad[0] = rec.pad[1] = rec.pad[2] = 0u;
    g_P16[v] = rec;

    VRec vr;
    vr.acc  = make_float4(0.f, 0.f, 0.f, 0.f);
    vr.self = make_float4(P9, t1s, t2s, 0.f);
    g_vs[v] = vr;
}

// ---------------------------------------------------------------------------
// Kernel 2: PDL. Pre-wait: stream loads + all trig. Post-wait: gather + RED.
// ---------------------------------------------------------------------------
__global__ void __launch_bounds__(256)
edge_kernel(const int* __restrict__ edge_index,
            const float* __restrict__ angles,
            const float* __restrict__ transporters) {
    int i = blockIdx.x * blockDim.x + threadIdx.x;   // quad index

    int4 s4, d4;
    float cdt[4], sdt[4], c2[4], s2[4], ct[4], st[4], cg[4], sg[4];

    if (i < NE / 4) {
        s4 = ((const int4*)edge_index)[i];
        d4 = ((const int4*)(edge_index + NE))[i];
        float4 t4 = ((const float4*)angles)[i];
        float4 g4 = ((const float4*)transporters)[i];
        float tv[4] = {t4.x, t4.y, t4.z, t4.w};
        float gv[4] = {g4.x, g4.y, g4.z, g4.w};
#pragma unroll
        for (int k = 0; k < 4; k++) {
            __sincosf(tv[k], &st[k], &ct[k]);
            __sincosf(gv[k], &sg[k], &cg[k]);
            cdt[k] = fmaf(ct[k], cg[k], st[k] * sg[k]);
            sdt[k] = fmaf(st[k], cg[k], -ct[k] * sg[k]);
            c2[k]  = fmaf(ct[k], cdt[k], -st[k] * sdt[k]);
            s2[k]  = fmaf(st[k], cdt[k], ct[k] * sdt[k]);
        }
    }

    pdl_wait();   // precompute results (g_P16, g_vs) now visible

    if (i >= NE / 4) { pdl_trigger(); return; }

    int srcs[4] = {s4.x, s4.y, s4.z, s4.w};
    int dsts[4] = {d4.x, d4.y, d4.z, d4.w};
#pragma unroll
    for (int k = 0; k < 4; k++) {
        const PRec16& pr = g_P16[srcs[k]];
        uint4 w = pr.w;
        unsigned int w4 = pr.w4;
        float  p0  = __uint_as_float(w.x);
        float2 p12 = __half22float2(*(const __half2*)&w.y);
        float2 p34 = __half22float2(*(const __half2*)&w.z);
        float2 p56 = __half22float2(*(const __half2*)&w.w);
        float2 p78 = __half22float2(*(const __half2*)&w4);

        float m0  = p0 + fmaf(p12.x, cdt[k], p12.y * sdt[k]);
        float mv1 = fmaf(p34.x, ct[k], -p34.y * st[k])
                  + fmaf(p56.x, cg[k], -p56.y * sg[k])
                  + fmaf(p78.x, c2[k], p78.y * s2[k]);
        float mv2 = fmaf(p34.x, st[k], p34.y * ct[k])
                  + fmaf(p56.x, sg[k], p56.y * cg[k])
                  + fmaf(-p78.y, c2[k], p78.x * s2[k]);

        asm volatile("red.relaxed.gpu.global.add.v4.f32 [%0], {%1, %2, %3, %4};"
                     :: "l"(&g_vs[dsts[k]].acc), "f"(m0), "f"(mv1), "f"(mv2),
                        "f"(1.0f) : "memory");
    }
    pdl_trigger();
}

// ---------------------------------------------------------------------------
// Kernel 3: PDL. Pre-wait: e1/e2 stream loads. Post-wait: g_vs + store.
// ---------------------------------------------------------------------------
__global__ void __launch_bounds__(256)
finalize_kernel(const float* __restrict__ e1,
                const float* __restrict__ e2,
                float* __restrict__ out) {
    int j = blockIdx.x * blockDim.x + threadIdx.x;

    float e1v = 0.f, e2v = 0.f;
    if (j < NV * 3) {
        e1v = e1[j];
        e2v = e2[j];
    }

    pdl_wait();   // edge-phase REDs now visible

    if (j >= NV * 3) return;
    int v = j / 3;

    VRec vr = g_vs[v];
    float inv = 1.0f / fmaxf(vr.acc.w, 1.0f);

    float mag = fmaf(vr.acc.x, inv, vr.self.x);
    float t1  = fmaf(vr.acc.y, inv, vr.self.y);
    float t2  = fmaf(vr.acc.z, inv, vr.self.z);
    float scale = 2.0f / (1.0f + __expf(-mag));

    out[j] = fmaf(t1, e1v, t2 * e2v) * scale;
}

extern "C" void kernel_launch(void* const* d_in, const int* in_sizes, int n_in,
                              void* d_out, int out_size) {
    const float* x            = (const float*)d_in[0];
    const int*   edge_index   = (const int*)d_in[1];
    const float* angles       = (const float*)d_in[2];
    const float* transporters = (const float*)d_in[3];
    const float* e1           = (const float*)d_in[4];
    const float* e2           = (const float*)d_in[5];
    const float* w_self0      = (const float*)d_in[6];
    const float* w_n00        = (const float*)d_in[7];
    const float* w_n10        = (const float*)d_in[8];
    const float* w_self11     = (const float*)d_in[9];
    const float* w_n01        = (const float*)d_in[10];
    const float* w_n11        = (const float*)d_in[11];
    float*       out          = (float*)d_out;

    // 1) precompute (plain launch; triggers dependents early)
    precompute_kernel<<<VERT_BLOCKS, 128>>>(x, w_self0, w_n00, w_n10,
                                            w_self11, w_n01, w_n11);

    // 2) edge kernel with programmatic dependent launch
    {
        cudaLaunchConfig_t cfg = {};
        cfg.gridDim  = dim3((NE / 4 + 255) / 256);
        cfg.blockDim = dim3(256);
        cfg.stream   = 0;
        cudaLaunchAttribute attr[1];
        attr[0].id = cudaLaunchAttributeProgrammaticStreamSerialization;
        attr[0].val.programmaticStreamSerializationAllowed = 1;
        cfg.attrs = attr;
        cfg.numAttrs = 1;
        cudaLaunchKernelEx(&cfg, edge_kernel, edge_index, angles, transporters);
    }

    // 3) finalize with programmatic dependent launch
    {
        cudaLaunchConfig_t cfg = {};
        cfg.gridDim  = dim3((NV * 3 + 255) / 256);
        cfg.blockDim = dim3(256);
        cfg.stream   = 0;
        cudaLaunchAttribute attr[1];
        attr[0].id = cudaLaunchAttributeProgrammaticStreamSerialization;
        attr[0].val.programmaticStreamSerializationAllowed = 1;
        cfg.attrs = attr;
        cfg.numAttrs = 1;
        cudaLaunchKernelEx(&cfg, finalize_kernel, e1, e2, out);
    }
}

// round 17
// speedup vs baseline: 1.2715x; 1.2279x over previous
#include <cuda_runtime.h>
#include <cuda_fp16.h>

#define NV 100000
#define NE 1600000
#define VERT_BLOCKS ((NV + 127) / 128)

// Packed per-vertex projection record: one 32B L2 sector per gather.
struct __align__(32) PRec16 {
    uint4 w;            // P0 fp32 | h2(P1,P2) | h2(P3,P4) | h2(P5,P6)
    unsigned int w4;    // h2(P7,P8)
    unsigned int pad[3];
};
struct __align__(32) VRec {
    float4 acc;   // (sum_m0, sum_mv1, sum_mv2, deg) — RED target
    float4 self;  // (selfMag, selfT1, selfT2, -)
};

__device__ PRec16 g_P16[NV];
__device__ VRec   g_vs[NV];

__device__ __forceinline__ unsigned int pack2(float a, float b) {
    __half2 h = __floats2half2_rn(a, b);
    return *(unsigned int*)&h;
}

// ---------------------------------------------------------------------------
// Kernel 1: per-vertex projections. Weights staged ONCE per block into smem,
// packed as float4 in exact consumption order; compute reads them via
// broadcast LDS.128. Per-thread LSU ops: 60 LDS.128 (was ~172 mixed ops).
//   swt[i]        i=0..15 : (w_n00[i], w_n01[2i], w_n01[2i+1], w_self0[i])
//   swt[16+2c+0]  c=0..15 : (w_n10[2c], w_n10[2c+1], w_self11[2c], w_self11[2c+1])
//   swt[16+2c+1]  c=0..15 : (w_n11[4c], w_n11[4c+1], w_n11[4c+2], w_n11[4c+3])
// ---------------------------------------------------------------------------
__global__ void __launch_bounds__(128)
precompute_kernel(const float* __restrict__ x,
                  const float* __restrict__ w_self0,
                  const float* __restrict__ w_n00,
                  const float* __restrict__ w_n10,
                  const float* __restrict__ w_self11,
                  const float* __restrict__ w_n01,
                  const float* __restrict__ w_n11) {
    __shared__ float4 sx4[128 * 13];
    __shared__ float4 swt[48];

    int base = blockIdx.x * 128;
    int nV = NV - base; if (nV > 128) nV = 128;

    // Stage weights (threads 0..47, one float4 each).
    int t = threadIdx.x;
    if (t < 16) {
        swt[t] = make_float4(__ldg(&w_n00[t]),
                             __ldg(&w_n01[2 * t + 0]),
                             __ldg(&w_n01[2 * t + 1]),
                             __ldg(&w_self0[t]));
    } else if (t < 48) {
        int idx = t - 16;
        int c = idx >> 1;
        if ((idx & 1) == 0) {
            swt[t] = make_float4(__ldg(&w_n10[2 * c + 0]),
                                 __ldg(&w_n10[2 * c + 1]),
                                 __ldg(&w_self11[2 * c + 0]),
                                 __ldg(&w_self11[2 * c + 1]));
        } else {
            swt[t] = *(const float4*)&w_n11[4 * c];
        }
    }

    // Stage x (coalesced float4, odd 16B-unit row stride = conflict-free).
    const float4* xg = (const float4*)(x + (size_t)base * 48);
    int nf4 = nV * 12;
    for (int j = threadIdx.x; j < nf4; j += 128) {
        sx4[(j / 12) * 13 + (j % 12)] = xg[j];
    }
    __syncthreads();

    int v = base + threadIdx.x;
    if (v >= NV) return;
    const float4* xv4 = &sx4[threadIdx.x * 13];

    // ---- x0 projections ----
    float P0 = 0.f, P3 = 0.f, P4 = 0.f, P9 = 0.f;
#pragma unroll
    for (int i4 = 0; i4 < 4; i4++) {
        float4 q = xv4[i4];
        float vals[4] = {q.x, q.y, q.z, q.w};
#pragma unroll
        for (int k = 0; k < 4; k++) {
            float4 w = swt[i4 * 4 + k];
            float xi = vals[k];
            P0 = fmaf(xi, w.x, P0);
            P3 = fmaf(xi, w.y, P3);
            P4 = fmaf(xi, w.z, P4);
            P9 = fmaf(xi, w.w, P9);
        }
    }

    // ---- x1 projections ----
    float a0 = 0.f, b0 = 0.f, a1 = 0.f, b1 = 0.f;
    float ap = 0.f, bp = 0.f, aq = 0.f, bq = 0.f;
    float ar = 0.f, br = 0.f, as_ = 0.f, bs = 0.f;
    float t1s = 0.f, t2s = 0.f;

#define CHAN(c, a, b)                                                \
    {                                                                \
        float4 wA = swt[16 + 2 * (c) + 0];  /* w0,w1,sa,sb */        \
        float4 wB = swt[16 + 2 * (c) + 1];  /* p,q,r,s */            \
        a0 = fmaf(a, wA.x, a0); b0 = fmaf(b, wA.x, b0);              \
        a1 = fmaf(a, wA.y, a1); b1 = fmaf(b, wA.y, b1);              \
        ap = fmaf(a, wB.x, ap); bp = fmaf(b, wB.x, bp);              \
        aq = fmaf(a, wB.y, aq); bq = fmaf(b, wB.y, bq);              \
        ar = fmaf(a, wB.z, ar); br = fmaf(b, wB.z, br);              \
        as_ = fmaf(a, wB.w, as_); bs = fmaf(b, wB.w, bs);            \
        t1s = fmaf(a, wA.z, t1s); t1s = fmaf(-(b), wA.w, t1s);       \
        t2s = fmaf(b, wA.z, t2s); t2s = fmaf(a, wA.w, t2s);          \
    }

#pragma unroll
    for (int c4 = 0; c4 < 8; c4++) {
        float4 q4 = xv4[4 + c4];
        CHAN(2 * c4 + 0, q4.x, q4.y)
        CHAN(2 * c4 + 1, q4.z, q4.w)
    }
#undef CHAN

    PRec16 rec;
    rec.w = make_uint4(__float_as_uint(P0),
                       pack2(a0 + b1, b0 - a1),     // (P1, P2)
                       pack2(P3, P4),               // (P3, P4)
                       pack2(ap - bq, bp + aq));    // (P5, P6)
    rec.w4 = pack2(ar + bs, br - as_);              // (P7, P8)
    rec.pad[0] = rec.pad[1] = rec.pad[2] = 0u;
    g_P16[v] = rec;

    VRec vr;
    vr.acc  = make_float4(0.f, 0.f, 0.f, 0.f);
    vr.self = make_float4(P9, t1s, t2s, 0.f);
    g_vs[v] = vr;
}

// ---------------------------------------------------------------------------
// Kernel 2: 4 edges per thread; single-sector fp16 gather; one v4 RED/edge.
// ---------------------------------------------------------------------------
__device__ __forceinline__ void edge_msg(int src, float t, float g,
                                         float& m0, float& mv1, float& mv2) {
    float st, ct, sg, cg;
    __sincosf(t, &st, &ct);
    __sincosf(g, &sg, &cg);
    float cdt = fmaf(ct, cg, st * sg);     // cos(t-g)
    float sdt = fmaf(st, cg, -ct * sg);    // sin(t-g)
    float c2 = fmaf(ct, cdt, -st * sdt);   // cos(2t-g)
    float s2 = fmaf(st, cdt, ct * sdt);    // sin(2t-g)

    const PRec16& pr = g_P16[src];
    uint4 w = pr.w;
    unsigned int w4 = pr.w4;
    float  p0  = __uint_as_float(w.x);
    float2 p12 = __half22float2(*(const __half2*)&w.y);
    float2 p34 = __half22float2(*(const __half2*)&w.z);
    float2 p56 = __half22float2(*(const __half2*)&w.w);
    float2 p78 = __half22float2(*(const __half2*)&w4);

    m0  = p0 + fmaf(p12.x, cdt, p12.y * sdt);
    mv1 = fmaf(p34.x, ct, -p34.y * st) + fmaf(p56.x, cg, -p56.y * sg)
        + fmaf(p78.x, c2, p78.y * s2);
    mv2 = fmaf(p34.x, st, p34.y * ct) + fmaf(p56.x, sg, p56.y * cg)
        + fmaf(-p78.y, c2, p78.x * s2);
}

__global__ void __launch_bounds__(256)
edge_kernel(const int* __restrict__ edge_index,
            const float* __restrict__ angles,
            const float* __restrict__ transporters) {
    int i = blockIdx.x * blockDim.x + threadIdx.x;   // quad index
    if (i >= NE / 4) return;

    int4   s4 = ((const int4*)edge_index)[i];
    int4   d4 = ((const int4*)(edge_index + NE))[i];
    float4 t4 = ((const float4*)angles)[i];
    float4 g4 = ((const float4*)transporters)[i];

    float m0, mv1, mv2;
#define DO_EDGE(SRC, DST, T, G)                                              \
    edge_msg(SRC, T, G, m0, mv1, mv2);                                       \
    asm volatile("red.relaxed.gpu.global.add.v4.f32 [%0], {%1, %2, %3, %4};" \
                 :: "l"(&g_vs[DST].acc), "f"(m0), "f"(mv1), "f"(mv2),        \
                    "f"(1.0f) : "memory");

    DO_EDGE(s4.x, d4.x, t4.x, g4.x)
    DO_EDGE(s4.y, d4.y, t4.y, g4.y)
    DO_EDGE(s4.z, d4.z, t4.z, g4.z)
    DO_EDGE(s4.w, d4.w, t4.w, g4.w)
#undef DO_EDGE
}

// ---------------------------------------------------------------------------
// Kernel 3: one thread per OUTPUT ELEMENT; single 32B record per vertex.
// ---------------------------------------------------------------------------
__global__ void __launch_bounds__(256)
finalize_kernel(const float* __restrict__ e1,
                const float* __restrict__ e2,
                float* __restrict__ out) {
    int j = blockIdx.x * blockDim.x + threadIdx.x;
    if (j >= NV * 3) return;
    int v = j / 3;

    VRec vr = g_vs[v];
    float inv = 1.0f / fmaxf(vr.acc.w, 1.0f);

    float mag = fmaf(vr.acc.x, inv, vr.self.x);
    float t1  = fmaf(vr.acc.y, inv, vr.self.y);
    float t2  = fmaf(vr.acc.z, inv, vr.self.z);
    float scale = 2.0f / (1.0f + __expf(-mag));

    out[j] = fmaf(t1, e1[j], t2 * e2[j]) * scale;
}

extern "C" void kernel_launch(void* const* d_in, const int* in_sizes, int n_in,
                              void* d_out, int out_size) {
    const float* x            = (const float*)d_in[0];
    const int*   edge_index   = (const int*)d_in[1];
    const float* angles       = (const float*)d_in[2];
    const float* transporters = (const float*)d_in[3];
    const float* e1           = (const float*)d_in[4];
    const float* e2           = (const float*)d_in[5];
    const float* w_self0      = (const float*)d_in[6];
    const float* w_n00        = (const float*)d_in[7];
    const float* w_n10        = (const float*)d_in[8];
    const float* w_self11     = (const float*)d_in[9];
    const float* w_n01        = (const float*)d_in[10];
    const float* w_n11        = (const float*)d_in[11];
    float*       out          = (float*)d_out;

    precompute_kernel<<<VERT_BLOCKS, 128>>>(x, w_self0, w_n00, w_n10,
                                            w_self11, w_n01, w_n11);
    edge_kernel<<<(NE / 4 + 255) / 256, 256>>>(edge_index, angles, transporters);
    finalize_kernel<<<(NV * 3 + 255) / 256, 256>>>(e1, e2, out);
}